// round 11
// baseline (speedup 1.0000x reference)
#include <cuda_runtime.h>
#include <cuda_fp16.h>

#define BB   256
#define TT   512
#define HH   128
#define G4   512
#define IND  10
#define XGR  16

typedef unsigned long long u64;

// ---------------- packed f32x2 helpers ----------------
__device__ __forceinline__ void ffma2(u64& acc, u64 a, u64 b) {
    asm("fma.rn.f32x2 %0, %1, %2, %0;" : "+l"(acc) : "l"(a), "l"(b));
}
__device__ __forceinline__ u64 pk(float lo, float hi) {
    u64 d; asm("mov.b64 %0, {%1, %2};" : "=l"(d) : "f"(lo), "f"(hi)); return d;
}
__device__ __forceinline__ float psum(u64 a) {
    float x, y; asm("mov.b64 {%0, %1}, %2;" : "=f"(x), "=f"(y) : "l"(a));
    return x + y;
}
__device__ __forceinline__ u64 h2u64(unsigned int h2bits) {
    __half2 h = *reinterpret_cast<__half2*>(&h2bits);
    float2 f = __half22float2(h);
    u64 d; asm("mov.b64 %0, {%1, %2};" : "=l"(d) : "f"(f.x), "f"(f.y)); return d;
}
__device__ __forceinline__ float tanhapx(float x) {
    float y; asm("tanh.approx.f32 %0, %1;" : "=f"(y) : "f"(x)); return y;
}
__device__ __forceinline__ float sigapx(float x) {
    return fmaf(0.5f, tanhapx(0.5f * x), 0.5f);
}

// ---------------- device-global scratch ----------------
// Pair mapping (R10): gate g -> slot=(g>>7)&1, t=((g&127)<<1)|(g>>8).
// Thread t owns gA=(t>>1)+(t&1)*256 (slot0), gB=gA+128 (slot1).
// g_whhpf: w_hh FP32, k in [64,128), pair-indexed float4:
//   [( (L*16 + ((k-64)>>2)) * 512 + slot*256 + t ) * 4 + ((k-64)&3)]
__device__ float  g_whhpf[2 * 16 * 512 * 4];
__device__ __half g_wih1h[G4 * HH];               // fp16 blocked, xgate only
__device__ float  g_h1[(size_t)BB * TT * HH];
__device__ float  g_xg1[(size_t)BB * TT * G4];
__device__ float  g_h2last[BB * HH];

__global__ void prep_kernel(const float* __restrict__ w_hh0,
                            const float* __restrict__ w_hh1,
                            const float* __restrict__ w_ih1)
{
    int idx = blockIdx.x * blockDim.x + threadIdx.x;   // 196608 threads
    if (idx >= 3 * G4 * HH) return;
    int m = idx >> 16;
    int e = idx & 65535;
    int g = e >> 7;
    int k = e & 127;
    if (m < 2) {
        if (k < 64) return;                            // k<64 read from w_hh directly
        int slot = (g >> 7) & 1;
        int t    = ((g & 127) << 1) | (g >> 8);
        int kk   = k - 64;
        float v  = (m ? w_hh1 : w_hh0)[e];
        g_whhpf[(((m * 16 + (kk >> 2)) * 512 + slot * 256 + t) << 2) + (kk & 3)] = v;
    } else {
        int dst = ((k >> 3) << 12) + (g << 3) + (k & 7);
        g_wih1h[dst] = __float2half(w_ih1[e]);
    }
}

// ---------------- LSTM recurrence (R10 shape, fp32 smem weights) ----------------
// 128 CTAs x 2 batch rows, 256 threads; thread t owns gates gA,gB both rows.
// k<64: fp32 weights in regs. k in [64,128): FP32 smem, pair-indexed (zero cvt,
// exact recurrence). shfl gate exchange, 1 barrier/step, tanh.approx acts.
// smem (bytes):
//   [0,131072)       w_hh fp32 float4 ws4[cc*512 + slot*256 + t], cc<16
//   [131072,151552)  wihp [10][2][256] fp32        (layer0 only)
//   [151552,153600)  biasp [2][256]                (layer0 only)
//   [153600,155648)  hs [2 buf][2 rows][128]
//   [155648,156160)  xs [2 buf][2 rows][16]        (layer0 only)
#define LSTM_SMEM 156160

template<int LAYER>
__global__ void __launch_bounds__(256, 1) lstm_layer_kernel(
    const float* __restrict__ x,
    const float* __restrict__ w_ih,
    const float* __restrict__ w_hh,
    const float* __restrict__ b_ih,
    const float* __restrict__ b_hh)
{
    extern __shared__ char smem[];
    float* ws    = (float*)smem;
    float* wihp  = (float*)(smem + 131072);
    float* biasp = (float*)(smem + 151552);
    float* hs    = (float*)(smem + 153600);
    float* xsb   = (float*)(smem + 155648);

    const int tid  = threadIdx.x;
    const int bb   = blockIdx.x;
    const int u    = tid >> 1;
    const int half = tid & 1;
    const int gA   = u + (half ? 256 : 0);
    const int gB   = gA + 128;

    // k<64 fp32 weights for both gates into registers (one-time LDG)
    u64 wreg0[32], wreg1[32];
    {
        const u64* wa = (const u64*)(w_hh + (size_t)gA * HH);
        const u64* wb = (const u64*)(w_hh + (size_t)gB * HH);
        #pragma unroll
        for (int i = 0; i < 32; i++) { wreg0[i] = wa[i]; wreg1[i] = wb[i]; }
    }

    // k in [64,128) fp32 weights into smem (pair-indexed, conflict-free)
    {
        float4*       ws4 = (float4*)ws;
        const float4* gw4 = (const float4*)g_whhpf;
        #pragma unroll
        for (int i = 0; i < 16; i++) {
            ws4[i * 512 + tid]       = gw4[(LAYER * 16 + i) * 512 + tid];
            ws4[i * 512 + 256 + tid] = gw4[(LAYER * 16 + i) * 512 + 256 + tid];
        }
    }

    if (LAYER == 0) {
        #pragma unroll
        for (int j = 0; j < IND; j++) {
            wihp[(j * 2 + 0) * 256 + tid] = w_ih[gA * IND + j];
            wihp[(j * 2 + 1) * 256 + tid] = w_ih[gB * IND + j];
        }
        biasp[tid]       = b_ih[gA] + b_hh[gA];
        biasp[256 + tid] = b_ih[gB] + b_hh[gB];
    }
    hs[tid] = 0.0f;                     // zero h buffer 0

    float c0 = 0.0f, c1 = 0.0f;

    float xgA0 = 0.0f, xgA1 = 0.0f, xgB0 = 0.0f, xgB1 = 0.0f;
    int xr = 0, xj = 0;
    if (LAYER == 0) {
        if (tid < 2 * IND) {
            xr = tid / IND; xj = tid - xr * IND;
            xsb[xr * 16 + xj] = x[(size_t)(2 * bb + xr) * (TT * IND) + xj];
        }
    } else {
        const float* p0 = g_xg1 + ((size_t)(2 * bb + 0) * TT + 0) * G4;
        const float* p1 = g_xg1 + ((size_t)(2 * bb + 1) * TT + 0) * G4;
        xgA0 = p0[gA]; xgB0 = p0[gB];
        xgA1 = p1[gA]; xgB1 = p1[gB];
    }
    __syncthreads();

    const ulonglong2* wsu = (const ulonglong2*)ws;   // index = float4 index

    for (int t = 0; t < TT; t++) {
        const int par = t & 1;
        const ulonglong2* h0v = (const ulonglong2*)(hs + par * 256);
        const ulonglong2* h1v = (const ulonglong2*)(hs + par * 256 + 128);
        float*            nxt = hs + (par ^ 1) * 256;
        const float*      xs  = xsb + par * 32;
        float*            xsn = xsb + (par ^ 1) * 32;

        // [A] prefetch next step's inputs
        float nx = 0.0f, nA0 = 0.0f, nA1 = 0.0f, nB0 = 0.0f, nB1 = 0.0f;
        if (LAYER == 0) {
            if (tid < 2 * IND && t + 1 < TT)
                nx = x[(size_t)(2 * bb + xr) * (TT * IND) + (size_t)(t + 1) * IND + xj];
        } else {
            if (t + 1 < TT) {
                const float* p0 = g_xg1 + ((size_t)(2 * bb + 0) * TT + (t + 1)) * G4;
                const float* p1 = g_xg1 + ((size_t)(2 * bb + 1) * TT + (t + 1)) * G4;
                nA0 = p0[gA]; nB0 = p0[gB];
                nA1 = p1[gA]; nB1 = p1[gB];
            }
        }

        // [B] initial scalar part
        float iA0, iA1, iB0, iB1;
        if (LAYER == 0) {
            float bvA = biasp[tid], bvB = biasp[256 + tid];
            iA0 = bvA; iA1 = bvA; iB0 = bvB; iB1 = bvB;
            #pragma unroll
            for (int j = 0; j < IND; j++) {
                float wAj = wihp[(j * 2 + 0) * 256 + tid];
                float wBj = wihp[(j * 2 + 1) * 256 + tid];
                float x0 = xs[j], x1 = xs[16 + j];
                iA0 = fmaf(x0, wAj, iA0);
                iA1 = fmaf(x1, wAj, iA1);
                iB0 = fmaf(x0, wBj, iB0);
                iB1 = fmaf(x1, wBj, iB1);
            }
        } else {
            iA0 = xgA0; iA1 = xgA1; iB0 = xgB0; iB1 = xgB1;
        }

        u64 aA0a = pk(iA0, 0.0f), aA0b = pk(0.0f, 0.0f);
        u64 aA1a = pk(iA1, 0.0f), aA1b = pk(0.0f, 0.0f);
        u64 aB0a = pk(iB0, 0.0f), aB0b = pk(0.0f, 0.0f);
        u64 aB1a = pk(iB1, 0.0f), aB1b = pk(0.0f, 0.0f);

        // k in [0,64): fp32 register weights
        #pragma unroll
        for (int i = 0; i < 16; i++) {
            ulonglong2 h0 = h0v[i];
            ulonglong2 h1 = h1v[i];
            ffma2(aA0a, h0.x, wreg0[2 * i]);
            ffma2(aA0b, h0.y, wreg0[2 * i + 1]);
            ffma2(aA1a, h1.x, wreg0[2 * i]);
            ffma2(aA1b, h1.y, wreg0[2 * i + 1]);
            ffma2(aB0a, h0.x, wreg1[2 * i]);
            ffma2(aB0b, h0.y, wreg1[2 * i + 1]);
            ffma2(aB1a, h1.x, wreg1[2 * i]);
            ffma2(aB1b, h1.y, wreg1[2 * i + 1]);
        }

        // k in [64,128): fp32 smem weights — zero conversions, exact
        #pragma unroll
        for (int c = 0; c < 8; c++) {
            ulonglong2 wA0 = wsu[(2 * c + 0) * 512 + tid];
            ulonglong2 wA1 = wsu[(2 * c + 1) * 512 + tid];
            ulonglong2 wB0 = wsu[(2 * c + 0) * 512 + 256 + tid];
            ulonglong2 wB1 = wsu[(2 * c + 1) * 512 + 256 + tid];
            ulonglong2 ha = h0v[16 + 2 * c];
            ulonglong2 hb = h0v[17 + 2 * c];
            ulonglong2 ka = h1v[16 + 2 * c];
            ulonglong2 kb = h1v[17 + 2 * c];
            ffma2(aA0a, ha.x, wA0.x); ffma2(aA0b, ha.y, wA0.y);
            ffma2(aA0a, hb.x, wA1.x); ffma2(aA0b, hb.y, wA1.y);
            ffma2(aA1a, ka.x, wA0.x); ffma2(aA1b, ka.y, wA0.y);
            ffma2(aA1a, kb.x, wA1.x); ffma2(aA1b, kb.y, wA1.y);
            ffma2(aB0a, ha.x, wB0.x); ffma2(aB0b, ha.y, wB0.y);
            ffma2(aB0a, hb.x, wB1.x); ffma2(aB0b, hb.y, wB1.y);
            ffma2(aB1a, ka.x, wB0.x); ffma2(aB1b, ka.y, wB0.y);
            ffma2(aB1a, kb.x, wB1.x); ffma2(aB1b, kb.y, wB1.y);
        }

        float vA0 = psum(aA0a) + psum(aA0b);
        float vA1 = psum(aA1a) + psum(aA1b);
        float vB0 = psum(aB0a) + psum(aB0b);
        float vB1 = psum(aB1a) + psum(aB1b);

        float pA0 = __shfl_xor_sync(0xffffffffu, vA0, 1);
        float pA1 = __shfl_xor_sync(0xffffffffu, vA1, 1);
        float pB0 = __shfl_xor_sync(0xffffffffu, vB0, 1);
        float pB1 = __shfl_xor_sync(0xffffffffu, vB1, 1);

        float gi0, gf0, gg0, go0, gi1, gf1, gg1, go1;
        if (half == 0) {
            gi0 = vA0; gf0 = vB0; gg0 = pA0; go0 = pB0;
            gi1 = vA1; gf1 = vB1; gg1 = pA1; go1 = pB1;
        } else {
            gi0 = pA0; gf0 = pB0; gg0 = vA0; go0 = vB0;
            gi1 = pA1; gf1 = pB1; gg1 = vA1; go1 = vB1;
        }

        c0 = sigapx(gf0) * c0 + sigapx(gi0) * tanhapx(gg0);
        c1 = sigapx(gf1) * c1 + sigapx(gi1) * tanhapx(gg1);
        float h0n = sigapx(go0) * tanhapx(c0);
        float h1n = sigapx(go1) * tanhapx(c1);

        if (half == 0) nxt[u]       = h0n;
        else           nxt[128 + u] = h1n;

        if (LAYER == 0) {
            g_h1[((size_t)(2 * bb + half) * TT + t) * HH + u] = half ? h1n : h0n;
        } else if (t == TT - 1) {
            g_h2last[(2 * bb + half) * HH + u] = half ? h1n : h0n;
        }

        if (LAYER == 0) {
            if (tid < 2 * IND) xsn[xr * 16 + xj] = nx;
        } else {
            xgA0 = nA0; xgA1 = nA1; xgB0 = nB0; xgB1 = nB1;
        }
        __syncthreads();
    }
}

// ---------------- layer-1 input projection GEMM (2 CTAs/SM, 2 k-passes) ----------------
// 8192 CTAs x 16 rows; 256 threads; thread = gates (tid, tid+256) x 16 rows.
// w tile split in two 64KB k-passes -> smem 72KB -> 2 resident CTAs/SM.
// regs: acc 32 u64 (64) + temps ~50 => fits the 124 cap at occupancy 2.
#define XG_SMEM (65536 + XGR * HH * 4)

__global__ void __launch_bounds__(256, 2) xgate1_kernel(
    const float* __restrict__ b_ih1, const float* __restrict__ b_hh1)
{
    extern __shared__ char smem[];
    __half* wsm = (__half*)smem;                 // half of w_ih1 per pass
    float*  h_s = (float*)(smem + 65536);        // 16 rows x 128

    const int tid = threadIdx.x;
    const int g0t = tid;
    const int g1t = tid + 256;

    uint4*       wsm4 = (uint4*)wsm;
    const uint4* gw4  = (const uint4*)g_wih1h;

    // h tile: 16 rows, loaded once
    const size_t base = (size_t)blockIdx.x * XGR * HH;
    {
        float4*       h_s4 = (float4*)h_s;
        const float4* src4 = (const float4*)(g_h1 + base);
        #pragma unroll
        for (int i = 0; i < (XGR * HH / 4) / 256; i++)
            h_s4[i * 256 + tid] = src4[i * 256 + tid];
    }

    float bvA = b_ih1[g0t] + b_hh1[g0t];
    float bvB = b_ih1[g1t] + b_hh1[g1t];
    u64 accA[XGR], accB[XGR];
    #pragma unroll
    for (int r = 0; r < XGR; r++) { accA[r] = pk(bvA, 0.0f); accB[r] = pk(bvB, 0.0f); }

    #pragma unroll
    for (int pass = 0; pass < 2; pass++) {
        if (pass) __syncthreads();               // drain pass-0 readers
        #pragma unroll
        for (int i = 0; i < 8; i++) {
            wsm4[i * 512 + g0t] = gw4[(pass * 8 + i) * 512 + g0t];
            wsm4[i * 512 + g1t] = gw4[(pass * 8 + i) * 512 + g1t];
        }
        __syncthreads();

        const int kb0 = pass * 64;
        #pragma unroll 1
        for (int c = 0; c < 8; c++) {
            uint4 wpA = wsm4[c * 512 + g0t];
            uint4 wpB = wsm4[c * 512 + g1t];
            u64 wA0 = h2u64(wpA.x), wA1 = h2u64(wpA.y);
            u64 wA2 = h2u64(wpA.z), wA3 = h2u64(wpA.w);
            u64 wB0 = h2u64(wpB.x), wB1 = h2u64(wpB.y);
            u64 wB2 = h2u64(wpB.z), wB3 = h2u64(wpB.w);
            const int kb = kb0 + c * 8;
            #pragma unroll
            for (int r = 0; r < XGR; r++) {
                ulonglong2 ha = *(const ulonglong2*)(h_s + r * HH + kb);
                ulonglong2 hb = *(const ulonglong2*)(h_s + r * HH + kb + 4);
                ffma2(accA[r], ha.x, wA0);
                ffma2(accA[r], ha.y, wA1);
                ffma2(accA[r], hb.x, wA2);
                ffma2(accA[r], hb.y, wA3);
                ffma2(accB[r], ha.x, wB0);
                ffma2(accB[r], ha.y, wB1);
                ffma2(accB[r], hb.x, wB2);
                ffma2(accB[r], hb.y, wB3);
            }
        }
    }

    #pragma unroll
    for (int r = 0; r < XGR; r++) {
        g_xg1[((size_t)blockIdx.x * XGR + r) * G4 + g0t] = psum(accA[r]);
        g_xg1[((size_t)blockIdx.x * XGR + r) * G4 + g1t] = psum(accB[r]);
    }
}

// ---------------- final FC ----------------
__global__ void fc_kernel(const float* __restrict__ fc_w,
                          const float* __restrict__ fc_b,
                          float* __restrict__ out)
{
    int b = threadIdx.x;
    const float* hrow = g_h2last + b * HH;
    #pragma unroll
    for (int c = 0; c < 10; c++) {
        float acc = fc_b[c];
        #pragma unroll
        for (int k = 0; k < HH; k++)
            acc = fmaf(hrow[k], fc_w[c * HH + k], acc);
        out[b * 10 + c] = acc;
    }
}

extern "C" void kernel_launch(void* const* d_in, const int* in_sizes, int n_in,
                              void* d_out, int out_size)
{
    const float* x     = (const float*)d_in[0];
    const float* w_ih0 = (const float*)d_in[1];
    const float* w_hh0 = (const float*)d_in[2];
    const float* b_ih0 = (const float*)d_in[3];
    const float* b_hh0 = (const float*)d_in[4];
    const float* w_ih1 = (const float*)d_in[5];
    const float* w_hh1 = (const float*)d_in[6];
    const float* b_ih1 = (const float*)d_in[7];
    const float* b_hh1 = (const float*)d_in[8];
    const float* fc_w  = (const float*)d_in[9];
    const float* fc_b  = (const float*)d_in[10];
    float* out = (float*)d_out;

    cudaFuncSetAttribute(lstm_layer_kernel<0>,
                         cudaFuncAttributeMaxDynamicSharedMemorySize, LSTM_SMEM);
    cudaFuncSetAttribute(lstm_layer_kernel<1>,
                         cudaFuncAttributeMaxDynamicSharedMemorySize, LSTM_SMEM);
    cudaFuncSetAttribute(xgate1_kernel,
                         cudaFuncAttributeMaxDynamicSharedMemorySize, XG_SMEM);

    prep_kernel<<<768, 256>>>(w_hh0, w_hh1, w_ih1);
    lstm_layer_kernel<0><<<BB / 2, 256, LSTM_SMEM>>>(x, w_ih0, w_hh0, b_ih0, b_hh0);
    xgate1_kernel<<<(BB * TT) / XGR, 256, XG_SMEM>>>(b_ih1, b_hh1);
    lstm_layer_kernel<1><<<BB / 2, 256, LSTM_SMEM>>>(nullptr, nullptr, w_hh1, nullptr, nullptr);
    fc_kernel<<<1, 256>>>(fc_w, fc_b, out);
}

// round 12
// speedup vs baseline: 1.0050x; 1.0050x over previous
#include <cuda_runtime.h>
#include <cuda_fp16.h>

#define BB   256
#define TT   512
#define HH   128
#define G4   512
#define IND  10

typedef unsigned long long u64;

// ---------------- packed f32x2 helpers ----------------
__device__ __forceinline__ void ffma2(u64& acc, u64 a, u64 b) {
    asm("fma.rn.f32x2 %0, %1, %2, %0;" : "+l"(acc) : "l"(a), "l"(b));
}
__device__ __forceinline__ u64 pk(float lo, float hi) {
    u64 d; asm("mov.b64 %0, {%1, %2};" : "=l"(d) : "f"(lo), "f"(hi)); return d;
}
__device__ __forceinline__ float psum(u64 a) {
    float x, y; asm("mov.b64 {%0, %1}, %2;" : "=f"(x), "=f"(y) : "l"(a));
    return x + y;
}
__device__ __forceinline__ u64 h2u64(unsigned int h2bits) {
    __half2 h = *reinterpret_cast<__half2*>(&h2bits);
    float2 f = __half22float2(h);
    u64 d; asm("mov.b64 %0, {%1, %2};" : "=l"(d) : "f"(f.x), "f"(f.y)); return d;
}
__device__ __forceinline__ float tanhapx(float x) {
    float y; asm("tanh.approx.f32 %0, %1;" : "=f"(y) : "f"(x)); return y;
}
__device__ __forceinline__ float sigapx(float x) {
    return fmaf(0.5f, tanhapx(0.5f * x), 0.5f);
}

// ---------------- device-global scratch ----------------
// Pair mapping: gate g -> slot=(g>>7)&1, t=((g&127)<<1)|(g>>8).
// Thread t owns gA=(t>>1)+(t&1)*256 (slot0), gB=gA+128 (slot1).
// g_whhph: w_hh fp16, k in [64,128), pair-indexed uint4 (8 halves):
//   [ ((L*8 + ((k-64)>>3))*512 + slot*256 + t)*8 + ((k-64)&7) ]
// g_wih1p: w_ih1 fp16, FULL k, pair-indexed uint4:
//   [ ((k>>3)*512 + slot*256 + t)*8 + (k&7) ]
__device__ __half g_whhph[2 * 8 * 512 * 8];
__device__ __half g_wih1p[16 * 512 * 8];
__device__ float  g_h1[(size_t)BB * TT * HH];
__device__ float  g_h2last[BB * HH];

__global__ void prep_kernel(const float* __restrict__ w_hh0,
                            const float* __restrict__ w_hh1,
                            const float* __restrict__ w_ih1)
{
    int idx = blockIdx.x * blockDim.x + threadIdx.x;   // 196608 threads
    if (idx >= 3 * G4 * HH) return;
    int m = idx >> 16;
    int e = idx & 65535;
    int g = e >> 7;
    int k = e & 127;
    int slot = (g >> 7) & 1;
    int t    = ((g & 127) << 1) | (g >> 8);
    if (m < 2) {
        if (k < 64) return;                            // k<64 read from w_hh directly
        float v = (m ? w_hh1 : w_hh0)[e];
        int kk = k - 64;
        g_whhph[(((m * 8 + (kk >> 3)) * 512 + slot * 256 + t) << 3) + (kk & 7)] =
            __float2half(v);
    } else {
        g_wih1p[(((k >> 3) * 512 + slot * 256 + t) << 3) + (k & 7)] =
            __float2half(w_ih1[e]);
    }
}

// ---------------- layer0 LSTM (EXACT R10 winner) ----------------
// 128 CTAs x 2 batch rows, 256 threads; thread t owns gates gA,gB both rows.
// smem: [0,65536) w_hh0 fp16 k>=64; [65536,86016) wihp; [86016,88064) biasp;
//       [88064,90112) hs 2buf; [90112,90368) xs 2buf.
#define L0_SMEM 90368

__global__ void __launch_bounds__(256, 1) lstm0_kernel(
    const float* __restrict__ x,
    const float* __restrict__ w_ih,
    const float* __restrict__ w_hh,
    const float* __restrict__ b_ih,
    const float* __restrict__ b_hh)
{
    extern __shared__ char smem[];
    __half* wsm   = (__half*)smem;
    float*  wihp  = (float*)(smem + 65536);
    float*  biasp = (float*)(smem + 86016);
    float*  hs    = (float*)(smem + 88064);
    float*  xsb   = (float*)(smem + 90112);

    const int tid  = threadIdx.x;
    const int bb   = blockIdx.x;
    const int u    = tid >> 1;
    const int half = tid & 1;
    const int gA   = u + (half ? 256 : 0);
    const int gB   = gA + 128;

    u64 wreg0[32], wreg1[32];
    {
        const u64* wa = (const u64*)(w_hh + (size_t)gA * HH);
        const u64* wb = (const u64*)(w_hh + (size_t)gB * HH);
        #pragma unroll
        for (int i = 0; i < 32; i++) { wreg0[i] = wa[i]; wreg1[i] = wb[i]; }
    }

    uint4*       ws4 = (uint4*)wsm;
    const uint4* gw4 = (const uint4*)g_whhph;
    #pragma unroll
    for (int i = 0; i < 8; i++) {
        ws4[i * 512 + tid]       = gw4[i * 512 + tid];
        ws4[i * 512 + 256 + tid] = gw4[i * 512 + 256 + tid];
    }

    #pragma unroll
    for (int j = 0; j < IND; j++) {
        wihp[(j * 2 + 0) * 256 + tid] = w_ih[gA * IND + j];
        wihp[(j * 2 + 1) * 256 + tid] = w_ih[gB * IND + j];
    }
    biasp[tid]       = b_ih[gA] + b_hh[gA];
    biasp[256 + tid] = b_ih[gB] + b_hh[gB];
    hs[tid] = 0.0f;

    float c0 = 0.0f, c1 = 0.0f;

    int xr = 0, xj = 0;
    if (tid < 2 * IND) {
        xr = tid / IND; xj = tid - xr * IND;
        xsb[xr * 16 + xj] = x[(size_t)(2 * bb + xr) * (TT * IND) + xj];
    }
    __syncthreads();

    for (int t = 0; t < TT; t++) {
        const int par = t & 1;
        const ulonglong2* h0v = (const ulonglong2*)(hs + par * 256);
        const ulonglong2* h1v = (const ulonglong2*)(hs + par * 256 + 128);
        float*            nxt = hs + (par ^ 1) * 256;
        const float*      xs  = xsb + par * 32;
        float*            xsn = xsb + (par ^ 1) * 32;

        float nx = 0.0f;
        if (tid < 2 * IND && t + 1 < TT)
            nx = x[(size_t)(2 * bb + xr) * (TT * IND) + (size_t)(t + 1) * IND + xj];

        float bvA = biasp[tid], bvB = biasp[256 + tid];
        float iA0 = bvA, iA1 = bvA, iB0 = bvB, iB1 = bvB;
        #pragma unroll
        for (int j = 0; j < IND; j++) {
            float wAj = wihp[(j * 2 + 0) * 256 + tid];
            float wBj = wihp[(j * 2 + 1) * 256 + tid];
            float x0 = xs[j], x1 = xs[16 + j];
            iA0 = fmaf(x0, wAj, iA0);
            iA1 = fmaf(x1, wAj, iA1);
            iB0 = fmaf(x0, wBj, iB0);
            iB1 = fmaf(x1, wBj, iB1);
        }

        u64 aA0a = pk(iA0, 0.0f), aA0b = pk(0.0f, 0.0f);
        u64 aA1a = pk(iA1, 0.0f), aA1b = pk(0.0f, 0.0f);
        u64 aB0a = pk(iB0, 0.0f), aB0b = pk(0.0f, 0.0f);
        u64 aB1a = pk(iB1, 0.0f), aB1b = pk(0.0f, 0.0f);

        #pragma unroll
        for (int i = 0; i < 16; i++) {
            ulonglong2 h0 = h0v[i];
            ulonglong2 h1 = h1v[i];
            ffma2(aA0a, h0.x, wreg0[2 * i]);
            ffma2(aA0b, h0.y, wreg0[2 * i + 1]);
            ffma2(aA1a, h1.x, wreg0[2 * i]);
            ffma2(aA1b, h1.y, wreg0[2 * i + 1]);
            ffma2(aB0a, h0.x, wreg1[2 * i]);
            ffma2(aB0b, h0.y, wreg1[2 * i + 1]);
            ffma2(aB1a, h1.x, wreg1[2 * i]);
            ffma2(aB1b, h1.y, wreg1[2 * i + 1]);
        }

        #pragma unroll
        for (int c = 0; c < 8; c++) {
            uint4 wpA = ws4[c * 512 + tid];
            uint4 wpB = ws4[c * 512 + 256 + tid];
            u64 wA0 = h2u64(wpA.x), wA1 = h2u64(wpA.y);
            u64 wA2 = h2u64(wpA.z), wA3 = h2u64(wpA.w);
            u64 wB0 = h2u64(wpB.x), wB1 = h2u64(wpB.y);
            u64 wB2 = h2u64(wpB.z), wB3 = h2u64(wpB.w);
            ulonglong2 ha = h0v[16 + 2 * c];
            ulonglong2 hb = h0v[17 + 2 * c];
            ulonglong2 ka = h1v[16 + 2 * c];
            ulonglong2 kb = h1v[17 + 2 * c];
            ffma2(aA0a, ha.x, wA0); ffma2(aA0b, ha.y, wA1);
            ffma2(aA0a, hb.x, wA2); ffma2(aA0b, hb.y, wA3);
            ffma2(aA1a, ka.x, wA0); ffma2(aA1b, ka.y, wA1);
            ffma2(aA1a, kb.x, wA2); ffma2(aA1b, kb.y, wA3);
            ffma2(aB0a, ha.x, wB0); ffma2(aB0b, ha.y, wB1);
            ffma2(aB0a, hb.x, wB2); ffma2(aB0b, hb.y, wB3);
            ffma2(aB1a, ka.x, wB0); ffma2(aB1b, ka.y, wB1);
            ffma2(aB1a, kb.x, wB2); ffma2(aB1b, kb.y, wB3);
        }

        float vA0 = psum(aA0a) + psum(aA0b);
        float vA1 = psum(aA1a) + psum(aA1b);
        float vB0 = psum(aB0a) + psum(aB0b);
        float vB1 = psum(aB1a) + psum(aB1b);

        float pA0 = __shfl_xor_sync(0xffffffffu, vA0, 1);
        float pA1 = __shfl_xor_sync(0xffffffffu, vA1, 1);
        float pB0 = __shfl_xor_sync(0xffffffffu, vB0, 1);
        float pB1 = __shfl_xor_sync(0xffffffffu, vB1, 1);

        float gi0, gf0, gg0, go0, gi1, gf1, gg1, go1;
        if (half == 0) {
            gi0 = vA0; gf0 = vB0; gg0 = pA0; go0 = pB0;
            gi1 = vA1; gf1 = vB1; gg1 = pA1; go1 = pB1;
        } else {
            gi0 = pA0; gf0 = pB0; gg0 = vA0; go0 = vB0;
            gi1 = pA1; gf1 = pB1; gg1 = vA1; go1 = vB1;
        }

        c0 = sigapx(gf0) * c0 + sigapx(gi0) * tanhapx(gg0);
        c1 = sigapx(gf1) * c1 + sigapx(gi1) * tanhapx(gg1);
        float h0n = sigapx(go0) * tanhapx(c0);
        float h1n = sigapx(go1) * tanhapx(c1);

        if (half == 0) nxt[u]       = h0n;
        else           nxt[128 + u] = h1n;

        g_h1[((size_t)(2 * bb + half) * TT + t) * HH + u] = half ? h1n : h0n;

        if (tid < 2 * IND) xsn[xr * 16 + xj] = nx;
        __syncthreads();
    }
}

// ---------------- layer1 FUSED: input projection + recurrence ----------------
// gates = bias + W_ih1 @ h1[t] + W_hh1 @ h2[t-1]  (one 256-long dot).
// Eliminates the xgate kernel and the 536MB g_xg1 DRAM round-trip.
// h1 streamed from g_h1 (1 float/thread/step, prefetched, double-buffered).
// w_hh1 k<64: fp32 regs. w_hh1 k>=64 + w_ih1 full: fp16 smem pair-indexed.
// smem: [0,131072) w_ih1; [131072,196608) w_hh1 hi; [196608,198656) biasp;
//       [198656,200704) h2s 2buf; [200704,202752) h1s 2buf.
#define L1_SMEM 202752

__global__ void __launch_bounds__(256, 1) lstm1_fused_kernel(
    const float* __restrict__ w_hh,
    const float* __restrict__ b_ih,
    const float* __restrict__ b_hh)
{
    extern __shared__ char smem[];
    __half* wih   = (__half*)smem;
    __half* whh   = (__half*)(smem + 131072);
    float*  biasp = (float*)(smem + 196608);
    float*  h2s   = (float*)(smem + 198656);
    float*  h1s   = (float*)(smem + 200704);

    const int tid  = threadIdx.x;
    const int bb   = blockIdx.x;
    const int u    = tid >> 1;
    const int half = tid & 1;
    const int gA   = u + (half ? 256 : 0);
    const int gB   = gA + 128;

    // w_hh1 k<64 fp32 into registers
    u64 wreg0[32], wreg1[32];
    {
        const u64* wa = (const u64*)(w_hh + (size_t)gA * HH);
        const u64* wb = (const u64*)(w_hh + (size_t)gB * HH);
        #pragma unroll
        for (int i = 0; i < 32; i++) { wreg0[i] = wa[i]; wreg1[i] = wb[i]; }
    }

    // smem weights (pair-indexed, conflict-free)
    uint4*       wih4 = (uint4*)wih;
    uint4*       whh4 = (uint4*)whh;
    {
        const uint4* gi4 = (const uint4*)g_wih1p;
        const uint4* gh4 = (const uint4*)g_whhph;
        #pragma unroll
        for (int i = 0; i < 16; i++) {
            wih4[i * 512 + tid]       = gi4[i * 512 + tid];
            wih4[i * 512 + 256 + tid] = gi4[i * 512 + 256 + tid];
        }
        #pragma unroll
        for (int i = 0; i < 8; i++) {
            whh4[i * 512 + tid]       = gh4[(8 + i) * 512 + tid];       // L=1
            whh4[i * 512 + 256 + tid] = gh4[(8 + i) * 512 + 256 + tid];
        }
    }

    biasp[tid]       = b_ih[gA] + b_hh[gA];
    biasp[256 + tid] = b_ih[gB] + b_hh[gB];
    h2s[tid] = 0.0f;                      // h2 buffer 0 = 0

    // h1[t=0] into h1s buffer 0: thread -> (row = tid>>7, unit = tid&127)
    const int r_ld = tid >> 7;
    const int u_ld = tid & 127;
    h1s[tid] = g_h1[((size_t)(2 * bb + r_ld) * TT + 0) * HH + u_ld];

    float c0 = 0.0f, c1 = 0.0f;
    __syncthreads();

    for (int t = 0; t < TT; t++) {
        const int par = t & 1;
        const ulonglong2* q0 = (const ulonglong2*)(h1s + par * 256);        // h1 row0
        const ulonglong2* q1 = (const ulonglong2*)(h1s + par * 256 + 128);  // h1 row1
        const ulonglong2* h0v = (const ulonglong2*)(h2s + par * 256);       // h2 row0
        const ulonglong2* h1v = (const ulonglong2*)(h2s + par * 256 + 128); // h2 row1
        float* h2n = h2s + (par ^ 1) * 256;
        float* h1n = h1s + (par ^ 1) * 256;

        // [A] prefetch h1[t+1]
        float nh1 = 0.0f;
        if (t + 1 < TT)
            nh1 = g_h1[((size_t)(2 * bb + r_ld) * TT + (t + 1)) * HH + u_ld];

        float bvA = biasp[tid], bvB = biasp[256 + tid];
        u64 aA0a = pk(bvA, 0.0f), aA0b = pk(0.0f, 0.0f);
        u64 aA1a = pk(bvA, 0.0f), aA1b = pk(0.0f, 0.0f);
        u64 aB0a = pk(bvB, 0.0f), aB0b = pk(0.0f, 0.0f);
        u64 aB1a = pk(bvB, 0.0f), aB1b = pk(0.0f, 0.0f);

        // [B1] W_ih1 @ h1[t]  (fp16 smem, full 128 k)
        #pragma unroll
        for (int c = 0; c < 16; c++) {
            uint4 wpA = wih4[c * 512 + tid];
            uint4 wpB = wih4[c * 512 + 256 + tid];
            u64 wA0 = h2u64(wpA.x), wA1 = h2u64(wpA.y);
            u64 wA2 = h2u64(wpA.z), wA3 = h2u64(wpA.w);
            u64 wB0 = h2u64(wpB.x), wB1 = h2u64(wpB.y);
            u64 wB2 = h2u64(wpB.z), wB3 = h2u64(wpB.w);
            ulonglong2 ha = q0[2 * c];
            ulonglong2 hb = q0[2 * c + 1];
            ulonglong2 ka = q1[2 * c];
            ulonglong2 kb = q1[2 * c + 1];
            ffma2(aA0a, ha.x, wA0); ffma2(aA0b, ha.y, wA1);
            ffma2(aA0a, hb.x, wA2); ffma2(aA0b, hb.y, wA3);
            ffma2(aA1a, ka.x, wA0); ffma2(aA1b, ka.y, wA1);
            ffma2(aA1a, kb.x, wA2); ffma2(aA1b, kb.y, wA3);
            ffma2(aB0a, ha.x, wB0); ffma2(aB0b, ha.y, wB1);
            ffma2(aB0a, hb.x, wB2); ffma2(aB0b, hb.y, wB3);
            ffma2(aB1a, ka.x, wB0); ffma2(aB1b, ka.y, wB1);
            ffma2(aB1a, kb.x, wB2); ffma2(aB1b, kb.y, wB3);
        }

        // [B2] W_hh1 @ h2[t-1], k<64: fp32 register weights
        #pragma unroll
        for (int i = 0; i < 16; i++) {
            ulonglong2 h0 = h0v[i];
            ulonglong2 h1 = h1v[i];
            ffma2(aA0a, h0.x, wreg0[2 * i]);
            ffma2(aA0b, h0.y, wreg0[2 * i + 1]);
            ffma2(aA1a, h1.x, wreg0[2 * i]);
            ffma2(aA1b, h1.y, wreg0[2 * i + 1]);
            ffma2(aB0a, h0.x, wreg1[2 * i]);
            ffma2(aB0b, h0.y, wreg1[2 * i + 1]);
            ffma2(aB1a, h1.x, wreg1[2 * i]);
            ffma2(aB1b, h1.y, wreg1[2 * i + 1]);
        }

        // [B3] W_hh1 @ h2[t-1], k in [64,128): fp16 smem
        #pragma unroll
        for (int c = 0; c < 8; c++) {
            uint4 wpA = whh4[c * 512 + tid];
            uint4 wpB = whh4[c * 512 + 256 + tid];
            u64 wA0 = h2u64(wpA.x), wA1 = h2u64(wpA.y);
            u64 wA2 = h2u64(wpA.z), wA3 = h2u64(wpA.w);
            u64 wB0 = h2u64(wpB.x), wB1 = h2u64(wpB.y);
            u64 wB2 = h2u64(wpB.z), wB3 = h2u64(wpB.w);
            ulonglong2 ha = h0v[16 + 2 * c];
            ulonglong2 hb = h0v[17 + 2 * c];
            ulonglong2 ka = h1v[16 + 2 * c];
            ulonglong2 kb = h1v[17 + 2 * c];
            ffma2(aA0a, ha.x, wA0); ffma2(aA0b, ha.y, wA1);
            ffma2(aA0a, hb.x, wA2); ffma2(aA0b, hb.y, wA3);
            ffma2(aA1a, ka.x, wA0); ffma2(aA1b, ka.y, wA1);
            ffma2(aA1a, kb.x, wA2); ffma2(aA1b, kb.y, wA3);
            ffma2(aB0a, ha.x, wB0); ffma2(aB0b, ha.y, wB1);
            ffma2(aB0a, hb.x, wB2); ffma2(aB0b, hb.y, wB3);
            ffma2(aB1a, ka.x, wB0); ffma2(aB1b, ka.y, wB1);
            ffma2(aB1a, kb.x, wB2); ffma2(aB1b, kb.y, wB3);
        }

        float vA0 = psum(aA0a) + psum(aA0b);
        float vA1 = psum(aA1a) + psum(aA1b);
        float vB0 = psum(aB0a) + psum(aB0b);
        float vB1 = psum(aB1a) + psum(aB1b);

        float pA0 = __shfl_xor_sync(0xffffffffu, vA0, 1);
        float pA1 = __shfl_xor_sync(0xffffffffu, vA1, 1);
        float pB0 = __shfl_xor_sync(0xffffffffu, vB0, 1);
        float pB1 = __shfl_xor_sync(0xffffffffu, vB1, 1);

        float gi0, gf0, gg0, go0, gi1, gf1, gg1, go1;
        if (half == 0) {
            gi0 = vA0; gf0 = vB0; gg0 = pA0; go0 = pB0;
            gi1 = vA1; gf1 = vB1; gg1 = pA1; go1 = pB1;
        } else {
            gi0 = pA0; gf0 = pB0; gg0 = vA0; go0 = vB0;
            gi1 = pA1; gf1 = pB1; gg1 = vA1; go1 = vB1;
        }

        c0 = sigapx(gf0) * c0 + sigapx(gi0) * tanhapx(gg0);
        c1 = sigapx(gf1) * c1 + sigapx(gi1) * tanhapx(gg1);
        float h0n = sigapx(go0) * tanhapx(c0);
        float h1nv = sigapx(go1) * tanhapx(c1);

        if (half == 0) h2n[u]       = h0n;
        else           h2n[128 + u] = h1nv;
        h1n[tid] = nh1;

        if (t == TT - 1)
            g_h2last[(2 * bb + half) * HH + u] = half ? h1nv : h0n;

        __syncthreads();
    }
}

// ---------------- final FC ----------------
__global__ void fc_kernel(const float* __restrict__ fc_w,
                          const float* __restrict__ fc_b,
                          float* __restrict__ out)
{
    int b = threadIdx.x;
    const float* hrow = g_h2last + b * HH;
    #pragma unroll
    for (int c = 0; c < 10; c++) {
        float acc = fc_b[c];
        #pragma unroll
        for (int k = 0; k < HH; k++)
            acc = fmaf(hrow[k], fc_w[c * HH + k], acc);
        out[b * 10 + c] = acc;
    }
}

extern "C" void kernel_launch(void* const* d_in, const int* in_sizes, int n_in,
                              void* d_out, int out_size)
{
    const float* x     = (const float*)d_in[0];
    const float* w_ih0 = (const float*)d_in[1];
    const float* w_hh0 = (const float*)d_in[2];
    const float* b_ih0 = (const float*)d_in[3];
    const float* b_hh0 = (const float*)d_in[4];
    const float* w_ih1 = (const float*)d_in[5];
    const float* w_hh1 = (const float*)d_in[6];
    const float* b_ih1 = (const float*)d_in[7];
    const float* b_hh1 = (const float*)d_in[8];
    const float* fc_w  = (const float*)d_in[9];
    const float* fc_b  = (const float*)d_in[10];
    float* out = (float*)d_out;

    cudaFuncSetAttribute(lstm0_kernel,
                         cudaFuncAttributeMaxDynamicSharedMemorySize, L0_SMEM);
    cudaFuncSetAttribute(lstm1_fused_kernel,
                         cudaFuncAttributeMaxDynamicSharedMemorySize, L1_SMEM);

    prep_kernel<<<768, 256>>>(w_hh0, w_hh1, w_ih1);
    lstm0_kernel<<<BB / 2, 256, L0_SMEM>>>(x, w_ih0, w_hh0, b_ih0, b_hh0);
    lstm1_fused_kernel<<<BB / 2, 256, L1_SMEM>>>(w_hh1, b_ih1, b_hh1);
    fc_kernel<<<1, 256>>>(fc_w, fc_b, out);
}

// round 13
// speedup vs baseline: 1.3817x; 1.3748x over previous
#include <cuda_runtime.h>
#include <cuda_fp16.h>

#define BB   256
#define TT   512
#define HH   128
#define G4   512
#define IND  10

typedef unsigned long long u64;

// ---------------- packed f32x2 helpers ----------------
__device__ __forceinline__ void ffma2(u64& acc, u64 a, u64 b) {
    asm("fma.rn.f32x2 %0, %1, %2, %0;" : "+l"(acc) : "l"(a), "l"(b));
}
__device__ __forceinline__ u64 pk(float lo, float hi) {
    u64 d; asm("mov.b64 %0, {%1, %2};" : "=l"(d) : "f"(lo), "f"(hi)); return d;
}
__device__ __forceinline__ float psum(u64 a) {
    float x, y; asm("mov.b64 {%0, %1}, %2;" : "=f"(x), "=f"(y) : "l"(a));
    return x + y;
}
__device__ __forceinline__ u64 h2u64(unsigned int h2bits) {
    __half2 h = *reinterpret_cast<__half2*>(&h2bits);
    float2 f = __half22float2(h);
    u64 d; asm("mov.b64 %0, {%1, %2};" : "=l"(d) : "f"(f.x), "f"(f.y)); return d;
}
__device__ __forceinline__ float tanhapx(float x) {
    float y; asm("tanh.approx.f32 %0, %1;" : "=f"(y) : "f"(x)); return y;
}
__device__ __forceinline__ float sigapx(float x) {
    return fmaf(0.5f, tanhapx(0.5f * x), 0.5f);
}

// ---------------- device-global scratch ----------------
// Pair mapping: gate g -> slot=(g>>7)&1, t=((g&127)<<1)|(g>>8).
// g_whhph: w_hh fp16, k in [64,128), pair-indexed uint4 (8 halves).
__device__ __half g_whhph[2 * 8 * 512 * 8];
__device__ __half g_wih1r[G4 * HH];               // w_ih1 fp16 row-major [512][128]
__device__ __half g_h1h[(size_t)BB * TT * HH];    // layer0 hidden, fp16
__device__ float  g_xg1[(size_t)BB * TT * G4];    // layer1 gate preacts fp32
__device__ float  g_h2last[BB * HH];

__global__ void prep_kernel(const float* __restrict__ w_hh0,
                            const float* __restrict__ w_hh1,
                            const float* __restrict__ w_ih1)
{
    int idx = blockIdx.x * blockDim.x + threadIdx.x;   // 196608 threads
    if (idx >= 3 * G4 * HH) return;
    int m = idx >> 16;
    int e = idx & 65535;
    int g = e >> 7;
    int k = e & 127;
    if (m < 2) {
        if (k < 64) return;                            // k<64 read from w_hh directly
        int slot = (g >> 7) & 1;
        int t    = ((g & 127) << 1) | (g >> 8);
        int kk   = k - 64;
        float v  = (m ? w_hh1 : w_hh0)[e];
        g_whhph[(((m * 8 + (kk >> 3)) * 512 + slot * 256 + t) << 3) + (kk & 7)] =
            __float2half(v);
    } else {
        g_wih1r[e] = __float2half(w_ih1[e]);
    }
}

// ---------------- LSTM recurrence (R10 winner; layer0 emits fp16 h1) ----------------
#define LSTM_SMEM 90368

template<int LAYER>
__global__ void __launch_bounds__(256, 1) lstm_layer_kernel(
    const float* __restrict__ x,
    const float* __restrict__ w_ih,
    const float* __restrict__ w_hh,
    const float* __restrict__ b_ih,
    const float* __restrict__ b_hh)
{
    extern __shared__ char smem[];
    __half* wsm   = (__half*)smem;
    float*  wihp  = (float*)(smem + 65536);
    float*  biasp = (float*)(smem + 86016);
    float*  hs    = (float*)(smem + 88064);
    float*  xsb   = (float*)(smem + 90112);

    const int tid  = threadIdx.x;
    const int bb   = blockIdx.x;
    const int u    = tid >> 1;
    const int half = tid & 1;
    const int gA   = u + (half ? 256 : 0);
    const int gB   = gA + 128;

    u64 wreg0[32], wreg1[32];
    {
        const u64* wa = (const u64*)(w_hh + (size_t)gA * HH);
        const u64* wb = (const u64*)(w_hh + (size_t)gB * HH);
        #pragma unroll
        for (int i = 0; i < 32; i++) { wreg0[i] = wa[i]; wreg1[i] = wb[i]; }
    }

    uint4*       ws4 = (uint4*)wsm;
    const uint4* gw4 = (const uint4*)g_whhph;
    #pragma unroll
    for (int i = 0; i < 8; i++) {
        ws4[i * 512 + tid]       = gw4[(LAYER * 8 + i) * 512 + tid];
        ws4[i * 512 + 256 + tid] = gw4[(LAYER * 8 + i) * 512 + 256 + tid];
    }

    if (LAYER == 0) {
        #pragma unroll
        for (int j = 0; j < IND; j++) {
            wihp[(j * 2 + 0) * 256 + tid] = w_ih[gA * IND + j];
            wihp[(j * 2 + 1) * 256 + tid] = w_ih[gB * IND + j];
        }
        biasp[tid]       = b_ih[gA] + b_hh[gA];
        biasp[256 + tid] = b_ih[gB] + b_hh[gB];
    }
    hs[tid] = 0.0f;

    float c0 = 0.0f, c1 = 0.0f;

    float xgA0 = 0.0f, xgA1 = 0.0f, xgB0 = 0.0f, xgB1 = 0.0f;
    int xr = 0, xj = 0;
    if (LAYER == 0) {
        if (tid < 2 * IND) {
            xr = tid / IND; xj = tid - xr * IND;
            xsb[xr * 16 + xj] = x[(size_t)(2 * bb + xr) * (TT * IND) + xj];
        }
    } else {
        const float* p0 = g_xg1 + ((size_t)(2 * bb + 0) * TT + 0) * G4;
        const float* p1 = g_xg1 + ((size_t)(2 * bb + 1) * TT + 0) * G4;
        xgA0 = p0[gA]; xgB0 = p0[gB];
        xgA1 = p1[gA]; xgB1 = p1[gB];
    }
    __syncthreads();

    for (int t = 0; t < TT; t++) {
        const int par = t & 1;
        const ulonglong2* h0v = (const ulonglong2*)(hs + par * 256);
        const ulonglong2* h1v = (const ulonglong2*)(hs + par * 256 + 128);
        float*            nxt = hs + (par ^ 1) * 256;
        const float*      xs  = xsb + par * 32;
        float*            xsn = xsb + (par ^ 1) * 32;

        float nx = 0.0f, nA0 = 0.0f, nA1 = 0.0f, nB0 = 0.0f, nB1 = 0.0f;
        if (LAYER == 0) {
            if (tid < 2 * IND && t + 1 < TT)
                nx = x[(size_t)(2 * bb + xr) * (TT * IND) + (size_t)(t + 1) * IND + xj];
        } else {
            if (t + 1 < TT) {
                const float* p0 = g_xg1 + ((size_t)(2 * bb + 0) * TT + (t + 1)) * G4;
                const float* p1 = g_xg1 + ((size_t)(2 * bb + 1) * TT + (t + 1)) * G4;
                nA0 = p0[gA]; nB0 = p0[gB];
                nA1 = p1[gA]; nB1 = p1[gB];
            }
        }

        float iA0, iA1, iB0, iB1;
        if (LAYER == 0) {
            float bvA = biasp[tid], bvB = biasp[256 + tid];
            iA0 = bvA; iA1 = bvA; iB0 = bvB; iB1 = bvB;
            #pragma unroll
            for (int j = 0; j < IND; j++) {
                float wAj = wihp[(j * 2 + 0) * 256 + tid];
                float wBj = wihp[(j * 2 + 1) * 256 + tid];
                float x0 = xs[j], x1 = xs[16 + j];
                iA0 = fmaf(x0, wAj, iA0);
                iA1 = fmaf(x1, wAj, iA1);
                iB0 = fmaf(x0, wBj, iB0);
                iB1 = fmaf(x1, wBj, iB1);
            }
        } else {
            iA0 = xgA0; iA1 = xgA1; iB0 = xgB0; iB1 = xgB1;
        }

        u64 aA0a = pk(iA0, 0.0f), aA0b = pk(0.0f, 0.0f);
        u64 aA1a = pk(iA1, 0.0f), aA1b = pk(0.0f, 0.0f);
        u64 aB0a = pk(iB0, 0.0f), aB0b = pk(0.0f, 0.0f);
        u64 aB1a = pk(iB1, 0.0f), aB1b = pk(0.0f, 0.0f);

        #pragma unroll
        for (int i = 0; i < 16; i++) {
            ulonglong2 h0 = h0v[i];
            ulonglong2 h1 = h1v[i];
            ffma2(aA0a, h0.x, wreg0[2 * i]);
            ffma2(aA0b, h0.y, wreg0[2 * i + 1]);
            ffma2(aA1a, h1.x, wreg0[2 * i]);
            ffma2(aA1b, h1.y, wreg0[2 * i + 1]);
            ffma2(aB0a, h0.x, wreg1[2 * i]);
            ffma2(aB0b, h0.y, wreg1[2 * i + 1]);
            ffma2(aB1a, h1.x, wreg1[2 * i]);
            ffma2(aB1b, h1.y, wreg1[2 * i + 1]);
        }

        #pragma unroll
        for (int c = 0; c < 8; c++) {
            uint4 wpA = ws4[c * 512 + tid];
            uint4 wpB = ws4[c * 512 + 256 + tid];
            u64 wA0 = h2u64(wpA.x), wA1 = h2u64(wpA.y);
            u64 wA2 = h2u64(wpA.z), wA3 = h2u64(wpA.w);
            u64 wB0 = h2u64(wpB.x), wB1 = h2u64(wpB.y);
            u64 wB2 = h2u64(wpB.z), wB3 = h2u64(wpB.w);
            ulonglong2 ha = h0v[16 + 2 * c];
            ulonglong2 hb = h0v[17 + 2 * c];
            ulonglong2 ka = h1v[16 + 2 * c];
            ulonglong2 kb = h1v[17 + 2 * c];
            ffma2(aA0a, ha.x, wA0); ffma2(aA0b, ha.y, wA1);
            ffma2(aA0a, hb.x, wA2); ffma2(aA0b, hb.y, wA3);
            ffma2(aA1a, ka.x, wA0); ffma2(aA1b, ka.y, wA1);
            ffma2(aA1a, kb.x, wA2); ffma2(aA1b, kb.y, wA3);
            ffma2(aB0a, ha.x, wB0); ffma2(aB0b, ha.y, wB1);
            ffma2(aB0a, hb.x, wB2); ffma2(aB0b, hb.y, wB3);
            ffma2(aB1a, ka.x, wB0); ffma2(aB1b, ka.y, wB1);
            ffma2(aB1a, kb.x, wB2); ffma2(aB1b, kb.y, wB3);
        }

        float vA0 = psum(aA0a) + psum(aA0b);
        float vA1 = psum(aA1a) + psum(aA1b);
        float vB0 = psum(aB0a) + psum(aB0b);
        float vB1 = psum(aB1a) + psum(aB1b);

        float pA0 = __shfl_xor_sync(0xffffffffu, vA0, 1);
        float pA1 = __shfl_xor_sync(0xffffffffu, vA1, 1);
        float pB0 = __shfl_xor_sync(0xffffffffu, vB0, 1);
        float pB1 = __shfl_xor_sync(0xffffffffu, vB1, 1);

        float gi0, gf0, gg0, go0, gi1, gf1, gg1, go1;
        if (half == 0) {
            gi0 = vA0; gf0 = vB0; gg0 = pA0; go0 = pB0;
            gi1 = vA1; gf1 = vB1; gg1 = pA1; go1 = pB1;
        } else {
            gi0 = pA0; gf0 = pB0; gg0 = vA0; go0 = vB0;
            gi1 = pA1; gf1 = pB1; gg1 = vA1; go1 = vB1;
        }

        c0 = sigapx(gf0) * c0 + sigapx(gi0) * tanhapx(gg0);
        c1 = sigapx(gf1) * c1 + sigapx(gi1) * tanhapx(gg1);
        float h0n = sigapx(go0) * tanhapx(c0);
        float h1n = sigapx(go1) * tanhapx(c1);

        if (half == 0) nxt[u]       = h0n;
        else           nxt[128 + u] = h1n;

        if (LAYER == 0) {
            g_h1h[((size_t)(2 * bb + half) * TT + t) * HH + u] =
                __float2half(half ? h1n : h0n);
        } else if (t == TT - 1) {
            g_h2last[(2 * bb + half) * HH + u] = half ? h1n : h0n;
        }

        if (LAYER == 0) {
            if (tid < 2 * IND) xsn[xr * 16 + xj] = nx;
        } else {
            xgA0 = nA0; xgA1 = nA1; xgB0 = nB0; xgB1 = nB1;
        }
        __syncthreads();
    }
}

// ---------------- xgate via tensor cores (mma.sync m16n8k16 f16->f32) ----------------
// xg1[m, n] = h1h[m,:] . w_ih1[n,:] + bias[n];  M=131072, N=512, K=128.
// Grid (1024, 4): 128x128 tile per CTA. 8 warps: warp w owns rows 16w..16w+15.
#define XG_PAD 136
#define XG_SMEM (2 * 128 * XG_PAD * 2 + 512)

__global__ void __launch_bounds__(256) xgate_mma_kernel(
    const float* __restrict__ b_ih1, const float* __restrict__ b_hh1)
{
    extern __shared__ char smem[];
    __half* As   = (__half*)smem;                          // [128][XG_PAD]
    __half* Bs   = (__half*)(smem + 128 * XG_PAD * 2);     // [128][XG_PAD]
    float*  bias = (float*)(smem + 2 * 128 * XG_PAD * 2);  // [128]

    const int tid = threadIdx.x;
    const int m0  = blockIdx.x * 128;
    const int n0  = blockIdx.y * 128;

    // load tiles (row-major contiguous k)
    {
        const uint4* src = (const uint4*)(g_h1h + (size_t)m0 * HH);
        const uint4* wsr = (const uint4*)(g_wih1r + (size_t)n0 * HH);
        #pragma unroll
        for (int i = 0; i < 8; i++) {
            int idx = i * 256 + tid;       // uint4 = 8 halves; 16 per row
            int row = idx >> 4;
            int kc  = (idx & 15) << 3;
            *(uint4*)(As + row * XG_PAD + kc) = src[idx];
            *(uint4*)(Bs + row * XG_PAD + kc) = wsr[idx];
        }
        if (tid < 128) bias[tid] = b_ih1[n0 + tid] + b_hh1[n0 + tid];
    }
    __syncthreads();

    const int warp = tid >> 5, lane = tid & 31;
    const int grp  = lane >> 2, tig = lane & 3;
    const int arow = warp * 16 + grp;

    // cache A fragments for all 8 k16-blocks (32 regs)
    unsigned int a[8][4];
    #pragma unroll
    for (int kk = 0; kk < 8; kk++) {
        const __half* base = As + arow * XG_PAD + kk * 16 + tig * 2;
        a[kk][0] = *(const unsigned int*)(base);
        a[kk][1] = *(const unsigned int*)(base + 8 * XG_PAD);
        a[kk][2] = *(const unsigned int*)(base + 8);
        a[kk][3] = *(const unsigned int*)(base + 8 * XG_PAD + 8);
    }

    #pragma unroll
    for (int j = 0; j < 16; j++) {
        float c0 = 0.f, c1 = 0.f, c2 = 0.f, c3 = 0.f;
        const __half* bbase = Bs + (j * 8 + grp) * XG_PAD + tig * 2;
        #pragma unroll
        for (int kk = 0; kk < 8; kk++) {
            unsigned int b0 = *(const unsigned int*)(bbase + kk * 16);
            unsigned int b1 = *(const unsigned int*)(bbase + kk * 16 + 8);
            asm volatile(
                "mma.sync.aligned.m16n8k16.row.col.f32.f16.f16.f32 "
                "{%0,%1,%2,%3}, {%4,%5,%6,%7}, {%8,%9}, {%0,%1,%2,%3};"
                : "+f"(c0), "+f"(c1), "+f"(c2), "+f"(c3)
                : "r"(a[kk][0]), "r"(a[kk][1]), "r"(a[kk][2]), "r"(a[kk][3]),
                  "r"(b0), "r"(b1));
        }
        int col = j * 8 + tig * 2;                       // local gate col
        float bv0 = bias[col], bv1 = bias[col + 1];
        float2* o0 = (float2*)(g_xg1 + (size_t)(m0 + arow)     * G4 + n0 + col);
        float2* o1 = (float2*)(g_xg1 + (size_t)(m0 + arow + 8) * G4 + n0 + col);
        *o0 = make_float2(c0 + bv0, c1 + bv1);
        *o1 = make_float2(c2 + bv0, c3 + bv1);
    }
}

// ---------------- final FC (warp per batch row) ----------------
__global__ void fc_kernel(const float* __restrict__ fc_w,
                          const float* __restrict__ fc_b,
                          float* __restrict__ out)
{
    int b    = blockIdx.x * 8 + (threadIdx.x >> 5);   // 32 CTAs x 8 warps = 256
    int lane = threadIdx.x & 31;
    float4 h = *(const float4*)(g_h2last + b * HH + lane * 4);
    #pragma unroll
    for (int c = 0; c < 10; c++) {
        float4 w = *(const float4*)(fc_w + c * HH + lane * 4);
        float p = h.x * w.x + h.y * w.y + h.z * w.z + h.w * w.w;
        #pragma unroll
        for (int s = 16; s > 0; s >>= 1)
            p += __shfl_xor_sync(0xffffffffu, p, s);
        if (lane == 0) out[b * 10 + c] = p + fc_b[c];
    }
}

extern "C" void kernel_launch(void* const* d_in, const int* in_sizes, int n_in,
                              void* d_out, int out_size)
{
    const float* x     = (const float*)d_in[0];
    const float* w_ih0 = (const float*)d_in[1];
    const float* w_hh0 = (const float*)d_in[2];
    const float* b_ih0 = (const float*)d_in[3];
    const float* b_hh0 = (const float*)d_in[4];
    const float* w_ih1 = (const float*)d_in[5];
    const float* w_hh1 = (const float*)d_in[6];
    const float* b_ih1 = (const float*)d_in[7];
    const float* b_hh1 = (const float*)d_in[8];
    const float* fc_w  = (const float*)d_in[9];
    const float* fc_b  = (const float*)d_in[10];
    float* out = (float*)d_out;

    cudaFuncSetAttribute(lstm_layer_kernel<0>,
                         cudaFuncAttributeMaxDynamicSharedMemorySize, LSTM_SMEM);
    cudaFuncSetAttribute(lstm_layer_kernel<1>,
                         cudaFuncAttributeMaxDynamicSharedMemorySize, LSTM_SMEM);
    cudaFuncSetAttribute(xgate_mma_kernel,
                         cudaFuncAttributeMaxDynamicSharedMemorySize, XG_SMEM);

    prep_kernel<<<768, 256>>>(w_hh0, w_hh1, w_ih1);
    lstm_layer_kernel<0><<<BB / 2, 256, LSTM_SMEM>>>(x, w_ih0, w_hh0, b_ih0, b_hh0);
    {
        dim3 grid(BB * TT / 128, G4 / 128);
        xgate_mma_kernel<<<grid, 256, XG_SMEM>>>(b_ih1, b_hh1);
    }
    lstm_layer_kernel<1><<<BB / 2, 256, LSTM_SMEM>>>(nullptr, nullptr, w_hh1, nullptr, nullptr);
    fc_kernel<<<32, 256>>>(fc_w, fc_b, out);
}

// round 15
// speedup vs baseline: 1.7018x; 1.2317x over previous
#include <cuda_runtime.h>
#include <cuda_fp16.h>

#define BB   256
#define TT   512
#define HH   128
#define G4   512
#define IND  10
#define RPC  8          // batch rows per CTA
#define HPAD 168        // halves per hbuf row

// ---------------- helpers ----------------
__device__ __forceinline__ float tanhapx(float x) {
    float y; asm("tanh.approx.f32 %0, %1;" : "=f"(y) : "f"(x)); return y;
}
__device__ __forceinline__ float sigapx(float x) {
    return fmaf(0.5f, tanhapx(0.5f * x), 0.5f);
}

// ---------------- device-global scratch ----------------
__device__ __half g_wA0[G4 * 144];               // [512][144] = [w_hh0 | w_ih0 pad16]
__device__ __half g_wA1[G4 * 128];               // [512][128] = w_hh1
__device__ __half g_wih1r[G4 * HH];              // w_ih1 row-major (xgate)
__device__ __half g_h1h[(size_t)BB * TT * HH];   // layer0 hidden, fp16
__device__ float  g_xg1[(size_t)BB * TT * G4];   // layer1 input-gate preacts (incl bias)
__device__ float  g_h2last[BB * HH];

__global__ void prep_kernel(const float* __restrict__ w_hh0,
                            const float* __restrict__ w_ih0,
                            const float* __restrict__ w_hh1,
                            const float* __restrict__ w_ih1)
{
    int idx = blockIdx.x * blockDim.x + threadIdx.x;   // 204800 threads
    if (idx < 73728) {                                  // g_wA0 [512][144]
        int g = idx / 144, k = idx - g * 144;
        float v = 0.0f;
        if (k < 128)       v = w_hh0[g * 128 + k];
        else if (k < 138)  v = w_ih0[g * 10 + (k - 128)];
        g_wA0[idx] = __float2half(v);
    } else if (idx < 139264) {                          // g_wA1 [512][128]
        int e = idx - 73728;
        g_wA1[e] = __float2half(w_hh1[e]);
    } else if (idx < 204800) {                          // g_wih1r
        int e = idx - 139264;
        g_wih1r[e] = __float2half(w_ih1[e]);
    }
}

// ---------------- LSTM recurrence on tensor cores ----------------
// 32 CTAs x 8 batch rows, 256 threads (8 warps).
// gates[512, 8] = A(W)[512, K] @ B(h^T)[K, 8];  K = 144 (L0: h|x) / 128 (L1).
// Warp w owns M-tiles {w, w+8, w+16, w+24} -> all 4 gates of units
// 16w+grp, 16w+grp+8 land in the SAME thread (no shuffles, no smem gates).
// A fragments: registers (loop-invariant). Bias: L0 only — L1 bias is
// already folded into g_xg1 by the xgate kernel (R14 bug: it was added twice).
template<int LAYER>
__global__ void __launch_bounds__(256, 1) lstm_mma_kernel(
    const float* __restrict__ x,
    const float* __restrict__ b_ih,
    const float* __restrict__ b_hh)
{
    constexpr int K    = (LAYER == 0) ? 144 : 128;
    constexpr int KBLK = K / 16;
    __shared__ __align__(16) __half hbuf[2][RPC][HPAD];

    const int tid  = threadIdx.x;
    const int bb   = blockIdx.x;
    const int warp = tid >> 5, lane = tid & 31;
    const int grp  = lane >> 2, tig = lane & 3;

    // zero both h buffers (h[-1] = 0, x pad = 0)
    for (int i = tid; i < 2 * RPC * HPAD; i += 256)
        ((__half*)hbuf)[i] = __float2half(0.0f);
    __syncthreads();                       // zero-fill visible before x[0] write

    // A fragments (weights) into registers — loop-invariant
    unsigned a[4][KBLK][4];
    const __half* Ag = (LAYER == 0) ? g_wA0 : g_wA1;
    #pragma unroll
    for (int tile = 0; tile < 4; tile++) {
        int mt = warp + tile * 8;
        int r0 = mt * 16 + grp, r1 = r0 + 8;
        #pragma unroll
        for (int kk = 0; kk < KBLK; kk++) {
            int c0 = kk * 16 + tig * 2;
            a[tile][kk][0] = *(const unsigned*)(Ag + r0 * K + c0);
            a[tile][kk][1] = *(const unsigned*)(Ag + r1 * K + c0);
            a[tile][kk][2] = *(const unsigned*)(Ag + r0 * K + c0 + 8);
            a[tile][kk][3] = *(const unsigned*)(Ag + r1 * K + c0 + 8);
        }
    }

    // bias — LAYER 0 only (layer1 bias already inside g_xg1)
    float bias[4][2];
    if (LAYER == 0) {
        #pragma unroll
        for (int tile = 0; tile < 4; tile++) {
            int g0 = (warp + tile * 8) * 16 + grp;
            bias[tile][0] = b_ih[g0]     + b_hh[g0];
            bias[tile][1] = b_ih[g0 + 8] + b_hh[g0 + 8];
        }
    }

    const int u1 = 16 * warp + grp;             // thread's units: u1, u1+8
    const int bA = 2 * tig, bB = 2 * tig + 1;   // thread's batch cols

    float cst[4] = {0.f, 0.f, 0.f, 0.f};

    // layer0: x[0] into hbuf[0] k-columns 128..137
    int xb = 0, xj = 0;
    if (LAYER == 0) {
        if (tid < RPC * IND) {
            xb = tid / IND; xj = tid - xb * IND;
            hbuf[0][xb][128 + xj] =
                __float2half(x[((size_t)(RPC * bb + xb) * TT + 0) * IND + xj]);
        }
    }
    // layer1: xg prefetch for t=0
    float xgp[4][4];
    if (LAYER == 1) {
        #pragma unroll
        for (int tile = 0; tile < 4; tile++) {
            int g0 = (warp + tile * 8) * 16 + grp;
            const float* p = g_xg1;
            xgp[tile][0] = p[((size_t)(RPC * bb + bA) * TT + 0) * G4 + g0];
            xgp[tile][1] = p[((size_t)(RPC * bb + bB) * TT + 0) * G4 + g0];
            xgp[tile][2] = p[((size_t)(RPC * bb + bA) * TT + 0) * G4 + g0 + 8];
            xgp[tile][3] = p[((size_t)(RPC * bb + bB) * TT + 0) * G4 + g0 + 8];
        }
    }
    __syncthreads();

    for (int t = 0; t < TT; t++) {
        const int cur = t & 1, nxt = cur ^ 1;

        // [A] prefetch next step's inputs
        float nx = 0.0f;
        float xgn[4][4];
        if (LAYER == 0) {
            if (tid < RPC * IND && t + 1 < TT)
                nx = x[((size_t)(RPC * bb + xb) * TT + (t + 1)) * IND + xj];
        } else {
            if (t + 1 < TT) {
                #pragma unroll
                for (int tile = 0; tile < 4; tile++) {
                    int g0 = (warp + tile * 8) * 16 + grp;
                    const float* p = g_xg1;
                    xgn[tile][0] = p[((size_t)(RPC * bb + bA) * TT + (t + 1)) * G4 + g0];
                    xgn[tile][1] = p[((size_t)(RPC * bb + bB) * TT + (t + 1)) * G4 + g0];
                    xgn[tile][2] = p[((size_t)(RPC * bb + bA) * TT + (t + 1)) * G4 + g0 + 8];
                    xgn[tile][3] = p[((size_t)(RPC * bb + bB) * TT + (t + 1)) * G4 + g0 + 8];
                }
            } else {
                #pragma unroll
                for (int tile = 0; tile < 4; tile++)
                    #pragma unroll
                    for (int j = 0; j < 4; j++) xgn[tile][j] = 0.0f;
            }
        }

        // [B] acc init — L0: bias; L1: xg (bias already inside)
        float acc[4][4];
        #pragma unroll
        for (int tile = 0; tile < 4; tile++) {
            if (LAYER == 0) {
                acc[tile][0] = bias[tile][0]; acc[tile][1] = bias[tile][0];
                acc[tile][2] = bias[tile][1]; acc[tile][3] = bias[tile][1];
            } else {
                acc[tile][0] = xgp[tile][0];
                acc[tile][1] = xgp[tile][1];
                acc[tile][2] = xgp[tile][2];
                acc[tile][3] = xgp[tile][3];
            }
        }

        // [C] mma over K: B frags shared across the 4 M-tiles
        #pragma unroll
        for (int kk = 0; kk < KBLK; kk++) {
            const __half* bp = &hbuf[cur][grp][kk * 16 + tig * 2];
            unsigned b0 = *(const unsigned*)bp;
            unsigned b1 = *(const unsigned*)(bp + 8);
            #pragma unroll
            for (int tile = 0; tile < 4; tile++) {
                asm volatile(
                    "mma.sync.aligned.m16n8k16.row.col.f32.f16.f16.f32 "
                    "{%0,%1,%2,%3}, {%4,%5,%6,%7}, {%8,%9}, {%0,%1,%2,%3};"
                    : "+f"(acc[tile][0]), "+f"(acc[tile][1]),
                      "+f"(acc[tile][2]), "+f"(acc[tile][3])
                    : "r"(a[tile][kk][0]), "r"(a[tile][kk][1]),
                      "r"(a[tile][kk][2]), "r"(a[tile][kk][3]),
                      "r"(b0), "r"(b1));
            }
        }

        // [D] activations — all 4 gates of each cell live in THIS thread
        float hn[4];
        #pragma unroll
        for (int cell = 0; cell < 4; cell++) {
            float gi = acc[0][cell], gf = acc[1][cell];
            float gg = acc[2][cell], go = acc[3][cell];
            cst[cell] = sigapx(gf) * cst[cell] + sigapx(gi) * tanhapx(gg);
            hn[cell]  = sigapx(go) * tanhapx(cst[cell]);
        }
        hbuf[nxt][bA][u1]     = __float2half(hn[0]);
        hbuf[nxt][bB][u1]     = __float2half(hn[1]);
        hbuf[nxt][bA][u1 + 8] = __float2half(hn[2]);
        hbuf[nxt][bB][u1 + 8] = __float2half(hn[3]);

        if (LAYER == 0) {
            if (tid < RPC * IND) hbuf[nxt][xb][128 + xj] = __float2half(nx);
        } else {
            #pragma unroll
            for (int tile = 0; tile < 4; tile++)
                #pragma unroll
                for (int j = 0; j < 4; j++) xgp[tile][j] = xgn[tile][j];
        }
        __syncthreads();

        if (LAYER == 0) {
            // export h[t] coalesced: warp = batch row, lane covers 4 units
            uint2 v = *(const uint2*)&hbuf[nxt][warp][lane * 4];
            *(uint2*)&g_h1h[((size_t)(RPC * bb + warp) * TT + t) * HH + lane * 4] = v;
        } else if (t == TT - 1) {
            g_h2last[(RPC * bb + bA) * HH + u1]     = hn[0];
            g_h2last[(RPC * bb + bB) * HH + u1]     = hn[1];
            g_h2last[(RPC * bb + bA) * HH + u1 + 8] = hn[2];
            g_h2last[(RPC * bb + bB) * HH + u1 + 8] = hn[3];
        }
    }
}

// ---------------- xgate via tensor cores (EXACT R13 version; bias folded here) ----------------
#define XG_PAD 136
#define XG_SMEM (2 * 128 * XG_PAD * 2 + 512)

__global__ void __launch_bounds__(256) xgate_mma_kernel(
    const float* __restrict__ b_ih1, const float* __restrict__ b_hh1)
{
    extern __shared__ char smem[];
    __half* As   = (__half*)smem;
    __half* Bs   = (__half*)(smem + 128 * XG_PAD * 2);
    float*  bias = (float*)(smem + 2 * 128 * XG_PAD * 2);

    const int tid = threadIdx.x;
    const int m0  = blockIdx.x * 128;
    const int n0  = blockIdx.y * 128;

    {
        const uint4* src = (const uint4*)(g_h1h + (size_t)m0 * HH);
        const uint4* wsr = (const uint4*)(g_wih1r + (size_t)n0 * HH);
        #pragma unroll
        for (int i = 0; i < 8; i++) {
            int idx = i * 256 + tid;
            int row = idx >> 4;
            int kc  = (idx & 15) << 3;
            *(uint4*)(As + row * XG_PAD + kc) = src[idx];
            *(uint4*)(Bs + row * XG_PAD + kc) = wsr[idx];
        }
        if (tid < 128) bias[tid] = b_ih1[n0 + tid] + b_hh1[n0 + tid];
    }
    __syncthreads();

    const int warp = tid >> 5, lane = tid & 31;
    const int grp  = lane >> 2, tig = lane & 3;
    const int arow = warp * 16 + grp;

    unsigned int a[8][4];
    #pragma unroll
    for (int kk = 0; kk < 8; kk++) {
        const __half* base = As + arow * XG_PAD + kk * 16 + tig * 2;
        a[kk][0] = *(const unsigned int*)(base);
        a[kk][1] = *(const unsigned int*)(base + 8 * XG_PAD);
        a[kk][2] = *(const unsigned int*)(base + 8);
        a[kk][3] = *(const unsigned int*)(base + 8 * XG_PAD + 8);
    }

    #pragma unroll
    for (int j = 0; j < 16; j++) {
        float c0 = 0.f, c1 = 0.f, c2 = 0.f, c3 = 0.f;
        const __half* bbase = Bs + (j * 8 + grp) * XG_PAD + tig * 2;
        #pragma unroll
        for (int kk = 0; kk < 8; kk++) {
            unsigned int b0 = *(const unsigned int*)(bbase + kk * 16);
            unsigned int b1 = *(const unsigned int*)(bbase + kk * 16 + 8);
            asm volatile(
                "mma.sync.aligned.m16n8k16.row.col.f32.f16.f16.f32 "
                "{%0,%1,%2,%3}, {%4,%5,%6,%7}, {%8,%9}, {%0,%1,%2,%3};"
                : "+f"(c0), "+f"(c1), "+f"(c2), "+f"(c3)
                : "r"(a[kk][0]), "r"(a[kk][1]), "r"(a[kk][2]), "r"(a[kk][3]),
                  "r"(b0), "r"(b1));
        }
        int col = j * 8 + tig * 2;
        float bv0 = bias[col], bv1 = bias[col + 1];
        float2* o0 = (float2*)(g_xg1 + (size_t)(m0 + arow)     * G4 + n0 + col);
        float2* o1 = (float2*)(g_xg1 + (size_t)(m0 + arow + 8) * G4 + n0 + col);
        *o0 = make_float2(c0 + bv0, c1 + bv1);
        *o1 = make_float2(c2 + bv0, c3 + bv1);
    }
}

// ---------------- final FC (warp per batch row) ----------------
__global__ void fc_kernel(const float* __restrict__ fc_w,
                          const float* __restrict__ fc_b,
                          float* __restrict__ out)
{
    int b    = blockIdx.x * 8 + (threadIdx.x >> 5);
    int lane = threadIdx.x & 31;
    float4 h = *(const float4*)(g_h2last + b * HH + lane * 4);
    #pragma unroll
    for (int c = 0; c < 10; c++) {
        float4 w = *(const float4*)(fc_w + c * HH + lane * 4);
        float p = h.x * w.x + h.y * w.y + h.z * w.z + h.w * w.w;
        #pragma unroll
        for (int s = 16; s > 0; s >>= 1)
            p += __shfl_xor_sync(0xffffffffu, p, s);
        if (lane == 0) out[b * 10 + c] = p + fc_b[c];
    }
}

extern "C" void kernel_launch(void* const* d_in, const int* in_sizes, int n_in,
                              void* d_out, int out_size)
{
    const float* x     = (const float*)d_in[0];
    const float* w_ih0 = (const float*)d_in[1];
    const float* w_hh0 = (const float*)d_in[2];
    const float* b_ih0 = (const float*)d_in[3];
    const float* b_hh0 = (const float*)d_in[4];
    const float* w_ih1 = (const float*)d_in[5];
    const float* w_hh1 = (const float*)d_in[6];
    const float* b_ih1 = (const float*)d_in[7];
    const float* b_hh1 = (const float*)d_in[8];
    const float* fc_w  = (const float*)d_in[9];
    const float* fc_b  = (const float*)d_in[10];
    float* out = (float*)d_out;

    cudaFuncSetAttribute(xgate_mma_kernel,
                         cudaFuncAttributeMaxDynamicSharedMemorySize, XG_SMEM);

    prep_kernel<<<800, 256>>>(w_hh0, w_ih0, w_hh1, w_ih1);
    lstm_mma_kernel<0><<<BB / RPC, 256>>>(x, b_ih0, b_hh0);
    {
        dim3 grid(BB * TT / 128, G4 / 128);
        xgate_mma_kernel<<<grid, 256, XG_SMEM>>>(b_ih1, b_hh1);
    }
    lstm_mma_kernel<1><<<BB / RPC, 256>>>(nullptr, b_ih1, b_hh1);
    fc_kernel<<<32, 256>>>(fc_w, fc_b, out);
}

// round 16
// speedup vs baseline: 2.2030x; 1.2945x over previous
#include <cuda_runtime.h>
#include <cuda_fp16.h>

#define BB   256
#define TT   512
#define HH   128
#define G4   512
#define IND  10
#define RPC  8          // batch rows per CTA
#define HPAD 168        // halves per hbuf row
#define XGP  516        // padded floats per xg smem row (bank-conflict-free)

// ---------------- helpers ----------------
__device__ __forceinline__ float tanhapx(float x) {
    float y; asm("tanh.approx.f32 %0, %1;" : "=f"(y) : "f"(x)); return y;
}
__device__ __forceinline__ float sigapx(float x) {
    return fmaf(0.5f, tanhapx(0.5f * x), 0.5f);
}

// ---------------- device-global scratch ----------------
__device__ __half g_wA0[G4 * 144];               // [512][144] = [w_hh0 | w_ih0 pad16]
__device__ __half g_wA1[G4 * 128];               // [512][128] = w_hh1
__device__ __half g_wih1r[G4 * HH];              // w_ih1 row-major (xgate)
__device__ __half g_h1h[(size_t)BB * TT * HH];   // layer0 hidden, fp16
// xg layout: [bb][t][b][g]  row = ((batch>>3)*512 + t)*8 + (batch&7), 512 floats/row
__device__ float  g_xg1[(size_t)BB * TT * G4];
__device__ float  g_h2last[BB * HH];

__global__ void prep_kernel(const float* __restrict__ w_hh0,
                            const float* __restrict__ w_ih0,
                            const float* __restrict__ w_hh1,
                            const float* __restrict__ w_ih1)
{
    int idx = blockIdx.x * blockDim.x + threadIdx.x;   // 204800 threads
    if (idx < 73728) {                                  // g_wA0 [512][144]
        int g = idx / 144, k = idx - g * 144;
        float v = 0.0f;
        if (k < 128)       v = w_hh0[g * 128 + k];
        else if (k < 138)  v = w_ih0[g * 10 + (k - 128)];
        g_wA0[idx] = __float2half(v);
    } else if (idx < 139264) {                          // g_wA1 [512][128]
        int e = idx - 73728;
        g_wA1[e] = __float2half(w_hh1[e]);
    } else if (idx < 204800) {                          // g_wih1r
        int e = idx - 139264;
        g_wih1r[e] = __float2half(w_ih1[e]);
    }
}

// ---------------- LSTM recurrence on tensor cores ----------------
// 32 CTAs x 8 batch rows, 256 threads (8 warps).
// gates[512, 8] = A(W)[512, K] @ B(h^T)[K, 8];  K = 144 (L0: h|x) / 128 (L1).
// Warp w owns M-tiles {w, w+8, w+16, w+24} -> all 4 gates of units
// 16w+grp, 16w+grp+8 in the SAME thread. A frags in registers.
// L1: xg block (16KB, contiguous) staged via smem, prefetched one step ahead.
template<int LAYER>
__global__ void __launch_bounds__(256, 1) lstm_mma_kernel(
    const float* __restrict__ x,
    const float* __restrict__ b_ih,
    const float* __restrict__ b_hh)
{
    constexpr int K    = (LAYER == 0) ? 144 : 128;
    constexpr int KBLK = K / 16;
    __shared__ __align__(16) __half hbuf[2][RPC][HPAD];
    __shared__ __align__(16) float  xgsm[2][RPC * XGP];   // used by LAYER==1 only

    const int tid  = threadIdx.x;
    const int bb   = blockIdx.x;
    const int warp = tid >> 5, lane = tid & 31;
    const int grp  = lane >> 2, tig = lane & 3;

    // zero both h buffers (h[-1] = 0, x pad = 0)
    for (int i = tid; i < 2 * RPC * HPAD; i += 256)
        ((__half*)hbuf)[i] = __float2half(0.0f);
    __syncthreads();                       // zero-fill visible before x[0] write

    // A fragments (weights) into registers — loop-invariant
    unsigned a[4][KBLK][4];
    const __half* Ag = (LAYER == 0) ? g_wA0 : g_wA1;
    #pragma unroll
    for (int tile = 0; tile < 4; tile++) {
        int mt = warp + tile * 8;
        int r0 = mt * 16 + grp, r1 = r0 + 8;
        #pragma unroll
        for (int kk = 0; kk < KBLK; kk++) {
            int c0 = kk * 16 + tig * 2;
            a[tile][kk][0] = *(const unsigned*)(Ag + r0 * K + c0);
            a[tile][kk][1] = *(const unsigned*)(Ag + r1 * K + c0);
            a[tile][kk][2] = *(const unsigned*)(Ag + r0 * K + c0 + 8);
            a[tile][kk][3] = *(const unsigned*)(Ag + r1 * K + c0 + 8);
        }
    }

    // bias — LAYER 0 only (layer1 bias already folded into g_xg1)
    float bias[4][2];
    if (LAYER == 0) {
        #pragma unroll
        for (int tile = 0; tile < 4; tile++) {
            int g0 = (warp + tile * 8) * 16 + grp;
            bias[tile][0] = b_ih[g0]     + b_hh[g0];
            bias[tile][1] = b_ih[g0 + 8] + b_hh[g0 + 8];
        }
    }

    const int u1 = 16 * warp + grp;             // thread's units: u1, u1+8
    const int bA = 2 * tig, bB = 2 * tig + 1;   // thread's batch cols

    float cst[4] = {0.f, 0.f, 0.f, 0.f};

    // layer0: x[0] into hbuf[0] k-columns 128..137
    int xb = 0, xj = 0;
    if (LAYER == 0) {
        if (tid < RPC * IND) {
            xb = tid / IND; xj = tid - xb * IND;
            hbuf[0][xb][128 + xj] =
                __float2half(x[((size_t)(RPC * bb + xb) * TT + 0) * IND + xj]);
        }
    }
    // layer1: stage xg block for t=0 into xgsm[0] (coalesced)
    if (LAYER == 1) {
        const uint4* src = (const uint4*)(g_xg1 + (size_t)bb * 512 * 4096);
        #pragma unroll
        for (int i = 0; i < 4; i++) {
            uint4 v = src[i * 256 + tid];
            int o = (i * 256 + tid) * 4;
            int b = o >> 9, g = o & 511;
            *(uint4*)&xgsm[0][b * XGP + g] = v;
        }
    }
    __syncthreads();

    for (int t = 0; t < TT; t++) {
        const int cur = t & 1, nxt = cur ^ 1;

        // [A] prefetch next step's inputs (latency hidden behind mma)
        float nx = 0.0f;
        uint4 ld[4];
        if (LAYER == 0) {
            if (tid < RPC * IND && t + 1 < TT)
                nx = x[((size_t)(RPC * bb + xb) * TT + (t + 1)) * IND + xj];
        } else {
            if (t + 1 < TT) {
                const uint4* src = (const uint4*)(g_xg1 +
                    ((size_t)bb * 512 + (t + 1)) * 4096);
                #pragma unroll
                for (int i = 0; i < 4; i++) ld[i] = src[i * 256 + tid];
            }
        }

        // [B] acc init — L0: bias; L1: xg from smem (zero-conflict pattern)
        float acc[4][4];
        #pragma unroll
        for (int tile = 0; tile < 4; tile++) {
            if (LAYER == 0) {
                acc[tile][0] = bias[tile][0]; acc[tile][1] = bias[tile][0];
                acc[tile][2] = bias[tile][1]; acc[tile][3] = bias[tile][1];
            } else {
                int g0 = (warp + tile * 8) * 16 + grp;
                acc[tile][0] = xgsm[cur][bA * XGP + g0];
                acc[tile][1] = xgsm[cur][bB * XGP + g0];
                acc[tile][2] = xgsm[cur][bA * XGP + g0 + 8];
                acc[tile][3] = xgsm[cur][bB * XGP + g0 + 8];
            }
        }

        // [C] mma over K: B frags shared across the 4 M-tiles
        #pragma unroll
        for (int kk = 0; kk < KBLK; kk++) {
            const __half* bp = &hbuf[cur][grp][kk * 16 + tig * 2];
            unsigned b0 = *(const unsigned*)bp;
            unsigned b1 = *(const unsigned*)(bp + 8);
            #pragma unroll
            for (int tile = 0; tile < 4; tile++) {
                asm volatile(
                    "mma.sync.aligned.m16n8k16.row.col.f32.f16.f16.f32 "
                    "{%0,%1,%2,%3}, {%4,%5,%6,%7}, {%8,%9}, {%0,%1,%2,%3};"
                    : "+f"(acc[tile][0]), "+f"(acc[tile][1]),
                      "+f"(acc[tile][2]), "+f"(acc[tile][3])
                    : "r"(a[tile][kk][0]), "r"(a[tile][kk][1]),
                      "r"(a[tile][kk][2]), "r"(a[tile][kk][3]),
                      "r"(b0), "r"(b1));
            }
        }

        // [D] activations — all 4 gates of each cell live in THIS thread
        float hn[4];
        #pragma unroll
        for (int cell = 0; cell < 4; cell++) {
            float gi = acc[0][cell], gf = acc[1][cell];
            float gg = acc[2][cell], go = acc[3][cell];
            cst[cell] = sigapx(gf) * cst[cell] + sigapx(gi) * tanhapx(gg);
            hn[cell]  = sigapx(go) * tanhapx(cst[cell]);
        }
        hbuf[nxt][bA][u1]     = __float2half(hn[0]);
        hbuf[nxt][bB][u1]     = __float2half(hn[1]);
        hbuf[nxt][bA][u1 + 8] = __float2half(hn[2]);
        hbuf[nxt][bB][u1 + 8] = __float2half(hn[3]);

        if (LAYER == 0) {
            if (tid < RPC * IND) hbuf[nxt][xb][128 + xj] = __float2half(nx);
        } else {
            if (t + 1 < TT) {
                #pragma unroll
                for (int i = 0; i < 4; i++) {
                    int o = (i * 256 + tid) * 4;
                    int b = o >> 9, g = o & 511;
                    *(uint4*)&xgsm[nxt][b * XGP + g] = ld[i];
                }
            }
        }
        __syncthreads();

        if (LAYER == 0) {
            // export h[t] coalesced: warp = batch row, lane covers 4 units
            uint2 v = *(const uint2*)&hbuf[nxt][warp][lane * 4];
            *(uint2*)&g_h1h[((size_t)(RPC * bb + warp) * TT + t) * HH + lane * 4] = v;
        } else if (t == TT - 1) {
            g_h2last[(RPC * bb + bA) * HH + u1]     = hn[0];
            g_h2last[(RPC * bb + bB) * HH + u1]     = hn[1];
            g_h2last[(RPC * bb + bA) * HH + u1 + 8] = hn[2];
            g_h2last[(RPC * bb + bB) * HH + u1 + 8] = hn[3];
        }
    }
}

// ---------------- xgate via tensor cores (R13 core; remapped output rows) ----------------
#define XG_PAD 136
#define XG_SMEM (2 * 128 * XG_PAD * 2 + 512)

__global__ void __launch_bounds__(256) xgate_mma_kernel(
    const float* __restrict__ b_ih1, const float* __restrict__ b_hh1)
{
    extern __shared__ char smem[];
    __half* As   = (__half*)smem;
    __half* Bs   = (__half*)(smem + 128 * XG_PAD * 2);
    float*  bias = (float*)(smem + 2 * 128 * XG_PAD * 2);

    const int tid = threadIdx.x;
    const int m0  = blockIdx.x * 128;
    const int n0  = blockIdx.y * 128;

    {
        const uint4* src = (const uint4*)(g_h1h + (size_t)m0 * HH);
        const uint4* wsr = (const uint4*)(g_wih1r + (size_t)n0 * HH);
        #pragma unroll
        for (int i = 0; i < 8; i++) {
            int idx = i * 256 + tid;
            int row = idx >> 4;
            int kc  = (idx & 15) << 3;
            *(uint4*)(As + row * XG_PAD + kc) = src[idx];
            *(uint4*)(Bs + row * XG_PAD + kc) = wsr[idx];
        }
        if (tid < 128) bias[tid] = b_ih1[n0 + tid] + b_hh1[n0 + tid];
    }
    __syncthreads();

    const int warp = tid >> 5, lane = tid & 31;
    const int grp  = lane >> 2, tig = lane & 3;
    const int arow = warp * 16 + grp;

    unsigned int a[8][4];
    #pragma unroll
    for (int kk = 0; kk < 8; kk++) {
        const __half* base = As + arow * XG_PAD + kk * 16 + tig * 2;
        a[kk][0] = *(const unsigned int*)(base);
        a[kk][1] = *(const unsigned int*)(base + 8 * XG_PAD);
        a[kk][2] = *(const unsigned int*)(base + 8);
        a[kk][3] = *(const unsigned int*)(base + 8 * XG_PAD + 8);
    }

    // output row remap: m = batch*512 + t  ->  row = ((batch>>3)*512 + t)*8 + (batch&7)
    const int mA    = m0 + arow;
    const int batch = mA >> 9, tA = mA & 511;
    const size_t rowA = ((size_t)(batch >> 3) * 512 + tA) * 8 + (batch & 7);
    const size_t rowB = rowA + 64;         // m+8 -> t+8 (same batch) -> +8*8 rows

    #pragma unroll
    for (int j = 0; j < 16; j++) {
        float c0 = 0.f, c1 = 0.f, c2 = 0.f, c3 = 0.f;
        const __half* bbase = Bs + (j * 8 + grp) * XG_PAD + tig * 2;
        #pragma unroll
        for (int kk = 0; kk < 8; kk++) {
            unsigned int b0 = *(const unsigned int*)(bbase + kk * 16);
            unsigned int b1 = *(const unsigned int*)(bbase + kk * 16 + 8);
            asm volatile(
                "mma.sync.aligned.m16n8k16.row.col.f32.f16.f16.f32 "
                "{%0,%1,%2,%3}, {%4,%5,%6,%7}, {%8,%9}, {%0,%1,%2,%3};"
                : "+f"(c0), "+f"(c1), "+f"(c2), "+f"(c3)
                : "r"(a[kk][0]), "r"(a[kk][1]), "r"(a[kk][2]), "r"(a[kk][3]),
                  "r"(b0), "r"(b1));
        }
        int col = j * 8 + tig * 2;
        float bv0 = bias[col], bv1 = bias[col + 1];
        float2* o0 = (float2*)(g_xg1 + rowA * G4 + n0 + col);
        float2* o1 = (float2*)(g_xg1 + rowB * G4 + n0 + col);
        *o0 = make_float2(c0 + bv0, c1 + bv1);
        *o1 = make_float2(c2 + bv0, c3 + bv1);
    }
}

// ---------------- final FC (warp per batch row) ----------------
__global__ void fc_kernel(const float* __restrict__ fc_w,
                          const float* __restrict__ fc_b,
                          float* __restrict__ out)
{
    int b    = blockIdx.x * 8 + (threadIdx.x >> 5);
    int lane = threadIdx.x & 31;
    float4 h = *(const float4*)(g_h2last + b * HH + lane * 4);
    #pragma unroll
    for (int c = 0; c < 10; c++) {
        float4 w = *(const float4*)(fc_w + c * HH + lane * 4);
        float p = h.x * w.x + h.y * w.y + h.z * w.z + h.w * w.w;
        #pragma unroll
        for (int s = 16; s > 0; s >>= 1)
            p += __shfl_xor_sync(0xffffffffu, p, s);
        if (lane == 0) out[b * 10 + c] = p + fc_b[c];
    }
}

extern "C" void kernel_launch(void* const* d_in, const int* in_sizes, int n_in,
                              void* d_out, int out_size)
{
    const float* x     = (const float*)d_in[0];
    const float* w_ih0 = (const float*)d_in[1];
    const float* w_hh0 = (const float*)d_in[2];
    const float* b_ih0 = (const float*)d_in[3];
    const float* b_hh0 = (const float*)d_in[4];
    const float* w_ih1 = (const float*)d_in[5];
    const float* w_hh1 = (const float*)d_in[6];
    const float* b_ih1 = (const float*)d_in[7];
    const float* b_hh1 = (const float*)d_in[8];
    const float* fc_w  = (const float*)d_in[9];
    const float* fc_b  = (const float*)d_in[10];
    float* out = (float*)d_out;

    cudaFuncSetAttribute(xgate_mma_kernel,
                         cudaFuncAttributeMaxDynamicSharedMemorySize, XG_SMEM);

    prep_kernel<<<800, 256>>>(w_hh0, w_ih0, w_hh1, w_ih1);
    lstm_mma_kernel<0><<<BB / RPC, 256>>>(x, b_ih0, b_hh0);
    {
        dim3 grid(BB * TT / 128, G4 / 128);
        xgate_mma_kernel<<<grid, 256, XG_SMEM>>>(b_ih1, b_hh1);
    }
    lstm_mma_kernel<1><<<BB / RPC, 256>>>(nullptr, b_ih1, b_hh1);
    fc_kernel<<<32, 256>>>(fc_w, fc_b, out);
}